// round 1
// baseline (speedup 1.0000x reference)
#include <cuda_runtime.h>
#include <cuda_bf16.h>

#define BINS 10

// Global scratch (allocation-free rule: __device__ globals).
__device__ float g_cnt[BINS];
__device__ float g_sum[BINS];

__global__ void zero_bins_k() {
    if (threadIdx.x < BINS) { g_cnt[threadIdx.x] = 0.0f; g_sum[threadIdx.x] = 0.0f; }
}

// Pass 1: streaming log-softmax + per-bin (count, ce-sum) accumulation.
// Layout: one warp handles 2 rows per iteration. Lane k loads float4 at
// columns 4*(k&15)..4*(k&15)+3 of row 2p+(k>>4): one coalesced 512B LDG.128
// per warp per iteration. Reductions are xor-shuffles with masks 1/2/4/8,
// which never cross the 16-lane half boundary.
__global__ __launch_bounds__(256, 8)
void ghm_pass1(const float4* __restrict__ x,
               const int*    __restrict__ target,
               const float*  __restrict__ weight,
               const int*    __restrict__ stage,
               int npairs)
{
    __shared__ float s_cnt[BINS];
    __shared__ float s_sum[BINS];
    const int tid = threadIdx.x;
    if (tid < BINS) { s_cnt[tid] = 0.0f; s_sum[tid] = 0.0f; }
    __syncthreads();

    const int lane = tid & 31;
    const int half = lane >> 4;   // 0: row 2p, 1: row 2p+1
    const int hl   = lane & 15;
    int w          = (blockIdx.x * blockDim.x + tid) >> 5;   // global warp id
    const int strd = (gridDim.x * blockDim.x) >> 5;          // total warps

    const int sraw = __ldg(stage);
    const bool stage1 = (sraw == 1) || (__int_as_float(sraw) == 1.0f);

    float cnt = 0.0f, csum = 0.0f;

    int p = w;
    float4 v = make_float4(0.f, 0.f, 0.f, 0.f);
    if (p < npairs) v = __ldg(x + (size_t)p * 32 + lane);

    while (p < npairs) {
        // software prefetch of next pair (MLP=2)
        const int pn = p + strd;
        float4 vn = make_float4(0.f, 0.f, 0.f, 0.f);
        if (pn < npairs) vn = __ldg(x + (size_t)pn * 32 + lane);

        const int row = 2 * p + half;
        const int t   = __ldg(target + row);           // broadcast within half

        // --- row max (within 16-lane half) ---
        float m = fmaxf(fmaxf(v.x, v.y), fmaxf(v.z, v.w));
        m = fmaxf(m, __shfl_xor_sync(0xffffffffu, m, 1));
        m = fmaxf(m, __shfl_xor_sync(0xffffffffu, m, 2));
        m = fmaxf(m, __shfl_xor_sync(0xffffffffu, m, 4));
        m = fmaxf(m, __shfl_xor_sync(0xffffffffu, m, 8));

        // --- sum exp(x - m) ---
        float s = __expf(v.x - m) + __expf(v.y - m)
                + __expf(v.z - m) + __expf(v.w - m);
        s += __shfl_xor_sync(0xffffffffu, s, 1);
        s += __shfl_xor_sync(0xffffffffu, s, 2);
        s += __shfl_xor_sync(0xffffffffu, s, 4);
        s += __shfl_xor_sync(0xffffffffu, s, 8);

        // --- gather x[row][t] via one shuffle from lane (half*16 + t/4) ---
        const int c = t & 3;
        const float sel = (c == 0) ? v.x : (c == 1) ? v.y : (c == 2) ? v.z : v.w;
        const float xt  = __shfl_sync(0xffffffffu, sel, (half << 4) + (t >> 2));

        // --- per-sample loss terms (uniform within each half) ---
        const float log_pt = xt - m - __logf(s);
        const float wt = stage1 ? 1.0f : __ldg(weight + t);
        const float ce = -wt * log_pt;
        const float g  = fabsf(__expf(log_pt) - 1.0f);
        int b = (int)(g * 9.9999f);          // floor(g * (BINS - 1e-4))
        b = min(max(b, 0), BINS - 1);

        // register-resident histogram: lane (hl==b) of each half owns bin b
        if (hl == b) { cnt += 1.0f; csum += ce; }

        v = vn; p = pn;
    }

    // fold the two halves' bin registers together
    cnt  += __shfl_xor_sync(0xffffffffu, cnt, 16);
    csum += __shfl_xor_sync(0xffffffffu, csum, 16);

    // per-block aggregation, then one global atomic per bin per block
    if (lane < BINS) {
        atomicAdd(&s_cnt[lane], cnt);
        atomicAdd(&s_sum[lane], csum);
    }
    __syncthreads();
    if (tid < BINS) {
        atomicAdd(&g_cnt[tid], s_cnt[tid]);
        atomicAdd(&g_sum[tid], s_sum[tid]);
    }
}

// Pass 2: tiny scalar finalize.
__global__ void finalize_k(float* __restrict__ out, float invN) {
    if (threadIdx.x == 0) {
        float nonempty = 0.0f;
        #pragma unroll
        for (int b = 0; b < BINS; b++)
            nonempty += (g_cnt[b] > 0.0f) ? 1.0f : 0.0f;
        float loss = 0.0f;
        #pragma unroll
        for (int b = 0; b < BINS; b++) {
            const float gd = fmaxf(g_cnt[b] * nonempty, 0.0001f);
            loss += g_sum[b] / gd;
        }
        out[0] = loss * invN;
    }
}

extern "C" void kernel_launch(void* const* d_in, const int* in_sizes, int n_in,
                              void* d_out, int out_size) {
    const float* x      = (const float*)d_in[0];
    const int*   target = (const int*)  d_in[1];
    const float* weight = (const float*)d_in[2];
    const int*   stage  = (const int*)  d_in[3];
    float*       out    = (float*)      d_out;

    const int N = in_sizes[1];        // number of samples (target count)
    const int npairs = N >> 1;        // two rows per warp-iteration

    zero_bins_k<<<1, 32>>>();
    ghm_pass1<<<1216, 256>>>((const float4*)x, target, weight, stage, npairs);
    finalize_k<<<1, 32>>>(out, 1.0f / (float)N);
}